// round 8
// baseline (speedup 1.0000x reference)
#include <cuda_runtime.h>
#include <cuda_fp16.h>
#include <math.h>
#include <float.h>

// Problem constants (fixed by the dataset)
#define NN 100000
#define EE 1200000
#define RR 3
#define M_TOT (RR * NN)
#define NBLK ((M_TOT + 1023) / 1024)       // 293
#define EDGE4 (RR * EE / 4)                 // 900000
#define NODE_BLKS ((NN + 127) / 128)        // 782
#define HIST_BLKS ((EDGE4 + 255) / 256)     // 3516
#define PQ_BLKS ((NN + 7) / 8)              // 12500

// ---------------- scratch (device globals; no allocation allowed) ----------
__device__ float   g_tfeat[NN * 64];
__device__ float4  g_hp[RR * NN * 16];        // hp fp32
__device__ __half2 g_hp16[RR * NN * 32];      // hp fp16 (128B gather rows)
__device__ float4  g_p[RR * NN];
__device__ float4  g_q[RR * NN];
__device__ float   g_gs[RR * NN];
__device__ float   g_res[NN * 192];
// CSR
__device__ int     g_deg[M_TOT];
__device__ int     g_row[M_TOT];              // global start; after build -> end
__device__ int     g_srt[RR * EE];
// lookback scan state
__device__ int     g_sagg[512];
__device__ int     g_spre[512];
__device__ int     g_sstat[512];              // 0 none, 1 agg, 2 prefix

__device__ __forceinline__ float lrelu(float x) { return x >= 0.f ? x : 0.01f * x; }

__device__ __forceinline__ unsigned long long pack2(float lo, float hi) {
    unsigned long long v;
    asm("mov.b64 %0, {%1,%2};" : "=l"(v) : "f"(lo), "f"(hi));
    return v;
}
__device__ __forceinline__ unsigned long long packbc(float x) {
    unsigned long long v;
    asm("mov.b64 %0, {%1,%1};" : "=l"(v) : "f"(x));
    return v;
}
__device__ __forceinline__ void ffma2(unsigned long long& d,
                                      unsigned long long a, unsigned long long b) {
    asm("fma.rn.f32x2 %0, %1, %2, %0;" : "+l"(d) : "l"(a), "l"(b));
}
__device__ __forceinline__ float2 unpack2(unsigned long long v) {
    float lo, hi;
    asm("mov.b64 {%0,%1}, %2;" : "=f"(lo), "=f"(hi) : "l"(v));
    return make_float2(lo, hi);
}

// ---------------- fat1: prep (blocks 0..781) + hist (rest) -----------------
__global__ __launch_bounds__(256) void k_fat1(
    const float* __restrict__ h, const float* __restrict__ d_w,
    const float* __restrict__ d_b, const float* __restrict__ w_w,
    const float* __restrict__ w_b, const int* __restrict__ dst)
{
    __shared__ float sHT[64 * 132];   // [k][n] padded
    __shared__ float sW[32 * 64];
    int tid = threadIdx.x;

    if (blockIdx.x >= NODE_BLKS) {
        int i = (blockIdx.x - NODE_BLKS) * 256 + tid;
        if (i < EDGE4) {
            int4 d4 = ((const int4*)dst)[i];
            int rb = (4 * i) / EE * NN;
            atomicAdd(&g_deg[rb + d4.x], 1);
            atomicAdd(&g_deg[rb + d4.y], 1);
            atomicAdd(&g_deg[rb + d4.z], 1);
            atomicAdd(&g_deg[rb + d4.w], 1);
        }
        return;
    }

    int base = blockIdx.x * 128;
    {
        int kk = tid & 63, nr = tid >> 6;
        for (int p = 0; p < 32; ++p) {
            int n = p * 4 + nr;
            int gn = base + n;
            sHT[kk * 132 + n] = (gn < NN) ? h[(size_t)gn * 64 + kk] : 0.f;
        }
    }
    int cx = (tid & 15) * 4;
    int ry = (tid >> 4) * 8;

    for (int mat = 0; mat < 4; ++mat) {
        const float* Wsrc = (mat == 0) ? d_w : (w_w + (mat - 1) * 4096);
        unsigned long long acc2[8][2];
        #pragma unroll
        for (int i = 0; i < 8; ++i) { acc2[i][0] = 0ull; acc2[i][1] = 0ull; }

        for (int kc = 0; kc < 2; ++kc) {
            __syncthreads();
            for (int i = tid; i < 2048; i += 256) sW[i] = Wsrc[kc * 2048 + i];
            __syncthreads();
            #pragma unroll 8
            for (int k = 0; k < 32; ++k) {
                const float* hr = &sHT[(kc * 32 + k) * 132 + ry];
                float4 a0 = *(const float4*)hr;
                float4 a1 = *(const float4*)(hr + 4);
                float4 b  = *(const float4*)&sW[k * 64 + cx];
                unsigned long long b01 = pack2(b.x, b.y);
                unsigned long long b23 = pack2(b.z, b.w);
                float av[8] = {a0.x, a0.y, a0.z, a0.w, a1.x, a1.y, a1.z, a1.w};
                #pragma unroll
                for (int i = 0; i < 8; ++i) {
                    unsigned long long aa = packbc(av[i]);
                    ffma2(acc2[i][0], aa, b01);
                    ffma2(acc2[i][1], aa, b23);
                }
            }
        }
        if (mat == 0) {
            float4 bia = *(const float4*)&d_b[cx];
            #pragma unroll
            for (int i = 0; i < 8; ++i) {
                int n = base + ry + i;
                if (n < NN) {
                    float2 v01 = unpack2(acc2[i][0]);
                    float2 v23 = unpack2(acc2[i][1]);
                    float4 t4;
                    t4.x = tanhf(2.f * (v01.x + bia.x));
                    t4.y = tanhf(2.f * (v01.y + bia.y));
                    t4.z = tanhf(2.f * (v23.x + bia.z));
                    t4.w = tanhf(2.f * (v23.y + bia.w));
                    *(float4*)&g_tfeat[(size_t)n * 64 + cx] = t4;
                }
            }
        } else {
            int r = mat - 1;
            float4 bia = *(const float4*)&w_b[r * 64 + cx];
            #pragma unroll
            for (int i = 0; i < 8; ++i) {
                int n = base + ry + i;
                if (n < NN) {
                    float2 v01 = unpack2(acc2[i][0]);
                    float2 v23 = unpack2(acc2[i][1]);
                    float4 hp4;
                    hp4.x = v01.x + bia.x;
                    hp4.y = v01.y + bia.y;
                    hp4.z = v23.x + bia.z;
                    hp4.w = v23.y + bia.w;
                    g_hp[((size_t)r * NN + n) * 16 + (cx >> 2)] = hp4;
                    __half2* p16 = &g_hp16[((size_t)r * NN + n) * 32 + (cx >> 1)];
                    p16[0] = __floats2half2_rn(hp4.x, hp4.y);
                    p16[1] = __floats2half2_rn(hp4.z, hp4.w);
                }
            }
        }
    }
}

// ---------------- single-pass decoupled-lookback scan -----------------------
__global__ __launch_bounds__(256) void k_scan() {
    __shared__ int sS[256];
    __shared__ int sExcl;
    int b = blockIdx.x;
    int tid = threadIdx.x;
    int base = b * 1024 + tid * 4;
    int v[4]; int s = 0;
    #pragma unroll
    for (int j = 0; j < 4; ++j) {
        v[j] = (base + j < M_TOT) ? g_deg[base + j] : 0;
        s += v[j];
    }
    sS[tid] = s;
    __syncthreads();
    for (int off = 1; off < 256; off <<= 1) {
        int t = (tid >= off) ? sS[tid - off] : 0;
        __syncthreads();
        sS[tid] += t;
        __syncthreads();
    }
    int run = sS[tid] - s;
    int bsum = sS[255];
    if (tid == 0) {
        *(volatile int*)&g_sagg[b] = bsum;
        __threadfence();
        *(volatile int*)&g_sstat[b] = 1;
        int excl = 0;
        if (b > 0) {
            int j = b - 1;
            while (true) {
                int st;
                while ((st = *(volatile int*)&g_sstat[j]) == 0) __nanosleep(40);
                if (st == 2) { excl += *(volatile int*)&g_spre[j]; break; }
                excl += *(volatile int*)&g_sagg[j];
                if (--j < 0) break;
            }
        }
        *(volatile int*)&g_spre[b] = excl + bsum;
        __threadfence();
        *(volatile int*)&g_sstat[b] = 2;
        sExcl = excl;
    }
    __syncthreads();
    int run2 = run + sExcl;
    #pragma unroll
    for (int j = 0; j < 4; ++j) {
        if (base + j < M_TOT) g_row[base + j] = run2;
        run2 += v[j];
    }
}

// ---------------- fat2: build (blocks 0..3515) + pq (rest) ------------------
__global__ __launch_bounds__(256) void k_fat2(
    const int* __restrict__ src, const int* __restrict__ dst,
    const float* __restrict__ atten_w, const float* __restrict__ atten_b,
    const float* __restrict__ beta)
{
    const unsigned FULL = 0xffffffffu;
    int tid = threadIdx.x;
    if (blockIdx.x < HIST_BLKS) {
        int i = blockIdx.x * 256 + tid;
        if (i >= EDGE4) return;
        int4 d4 = ((const int4*)dst)[i];
        int4 s4 = ((const int4*)src)[i];
        int rb = (4 * i) / EE * NN;
        g_srt[atomicAdd(&g_row[rb + d4.x], 1)] = s4.x;
        g_srt[atomicAdd(&g_row[rb + d4.y], 1)] = s4.y;
        g_srt[atomicAdd(&g_row[rb + d4.z], 1)] = s4.z;
        g_srt[atomicAdd(&g_row[rb + d4.w], 1)] = s4.w;
        return;
    }
    int n = (blockIdx.x - HIST_BLKS) * 8 + (tid >> 5);
    int lane = tid & 31;
    if (n >= NN) return;
    float t0 = g_tfeat[(size_t)n * 64 + lane];
    float t1 = g_tfeat[(size_t)n * 64 + 32 + lane];
    int j = lane & 15;
    #pragma unroll
    for (int r = 0; r < RR; ++r) {
        const float* hp = (const float*)&g_hp[((size_t)r * NN + n) * 16];
        float h0 = hp[lane], h1 = hp[lane + 32];
        float wa0 = __ldg(atten_w + r * 48 + j);
        float wa1 = __ldg(atten_w + r * 48 + 16 + j);
        float wa2 = __ldg(atten_w + r * 48 + 32 + j);
        float pA = h0 * wa0 + t0 * wa2;
        float pB = h1 * wa0 + t1 * wa2;
        float qA = h0 * wa1;
        float qB = h1 * wa1;
        #pragma unroll
        for (int s = 8; s; s >>= 1) {
            pA += __shfl_xor_sync(FULL, pA, s, 16);
            pB += __shfl_xor_sync(FULL, pB, s, 16);
            qA += __shfl_xor_sync(FULL, qA, s, 16);
            qB += __shfl_xor_sync(FULL, qB, s, 16);
        }
        float gsv = t0 * __ldg(beta + r * 128 + lane)
                  + t1 * __ldg(beta + r * 128 + 32 + lane);
        #pragma unroll
        for (int s = 16; s; s >>= 1) gsv += __shfl_xor_sync(FULL, gsv, s);
        if (j == 0) {
            int hh = lane >> 4;
            float ab = __ldg(atten_b + r);
            float* pp = (float*)&g_p[(size_t)r * NN + n];
            pp[hh]     = pA + ab;
            pp[hh + 2] = pB + ab;
            float* qq = (float*)&g_q[(size_t)r * NN + n];
            qq[hh]     = qA;
            qq[hh + 2] = qB;
        }
        if (lane == 0) g_gs[(size_t)r * NN + n] = gsv;
    }
}

// ---------------- aggregate: warp per (node, relation), high-MLP ------------
// superchunk of 32 edges: s_all loaded lane-per-edge (1 coalesced LDG),
// all p-loads + all hp16 gathers issued with addresses depending only on
// s_all -> ~13 outstanding loads per lane instead of ~2.
__global__ __launch_bounds__(256) void k_aggr(const float* __restrict__ beta)
{
    const unsigned FULL = 0xffffffffu;
    int warp = threadIdx.x >> 5;
    int lane = threadIdx.x & 31;
    int n = blockIdx.x * 8 + warp;
    int r = blockIdx.y;
    if (n >= NN) return;
    int idx = r * NN + n;
    int deg = g_deg[idx];
    int end = g_row[idx];            // build turned start -> end
    int start = end - deg;

    int m   = lane & 7;              // dim group: dims 8m..8m+7
    int qtr = lane >> 3;             // edge sub-slot in gather groups
    float qc = __ldg((const float*)g_q + (size_t)idx * 4 + (lane & 3));

    float acc[8];
    #pragma unroll
    for (int i = 0; i < 8; ++i) acc[i] = 0.f;
    float denacc = 0.f;
    float gsacc = 0.f;

    const float* pbase  = (const float*)g_p + (size_t)r * NN * 4;
    const float* gsbase = g_gs + (size_t)r * NN;
    const uint4* hpbase16 = (const uint4*)g_hp16 + (size_t)r * NN * 8;

    for (int sc = 0; sc < deg; sc += 32) {
        int cnt = deg - sc; if (cnt > 32) cnt = 32;
        // all edge ids for this superchunk, one coalesced load
        int s_all = (lane < cnt) ? __ldg(g_srt + start + sc + lane) : 0;
        // gs gather (parallel, 32 scattered scalar loads)
        gsacc += (lane < cnt) ? __ldg(gsbase + s_all) : 0.f;
        // p loads + exp for 4 chunks of 8 edges (lane = 4*edgeInChunk + head)
        float exc[4];
        #pragma unroll
        for (int c = 0; c < 4; ++c) {
            int eo = c * 8 + (lane >> 2);
            int sx = __shfl_sync(FULL, s_all, eo);
            float pl = __ldg(pbase + (size_t)sx * 4 + (lane & 3));
            exc[c] = (eo < cnt) ? __expf(lrelu(pl + qc)) : 0.f;
            denacc += exc[c];
        }
        // hp16 gather: 8 groups x 4 edges, 8 lanes (m) per edge row
        int nit = (cnt + 3) >> 2;
        #pragma unroll
        for (int g = 0; g < 8; ++g) {
            if (g >= nit) break;                           // warp-uniform
            int e0 = g * 4 + qtr;                          // edge 0..31
            int   sj = __shfl_sync(FULL, s_all, e0);
            float e  = __shfl_sync(FULL, exc[g >> 1],
                                   16 * (g & 1) + 4 * qtr + (m >> 1));
            uint4 hv = __ldg(hpbase16 + (size_t)sj * 8 + m);
            float2 f0 = __half22float2(*(const __half2*)&hv.x);
            float2 f1 = __half22float2(*(const __half2*)&hv.y);
            float2 f2 = __half22float2(*(const __half2*)&hv.z);
            float2 f3 = __half22float2(*(const __half2*)&hv.w);
            acc[0] += e * f0.x; acc[1] += e * f0.y;
            acc[2] += e * f1.x; acc[3] += e * f1.y;
            acc[4] += e * f2.x; acc[5] += e * f2.y;
            acc[6] += e * f3.x; acc[7] += e * f3.y;
        }
    }
    // denom per head (lanes sharing lane&3 across edge slots: bits 2..4)
    #pragma unroll
    for (int s = 4; s < 32; s <<= 1) denacc += __shfl_xor_sync(FULL, denacc, s);
    float d = __shfl_sync(FULL, denacc, m >> 1);
    // merge the 4 quarter edge-sets
    #pragma unroll
    for (int i = 0; i < 8; ++i) {
        acc[i] += __shfl_xor_sync(FULL, acc[i], 8);
        acc[i] += __shfl_xor_sync(FULL, acc[i], 16);
    }
    float inv = 1.f / fmaxf(d, 1e-20f);
    float o[8];
    #pragma unroll
    for (int i = 0; i < 8; ++i) o[i] = acc[i] * inv;
    // gs total (all 32 lanes contributed, full reduce)
    #pragma unroll
    for (int s = 16; s; s >>= 1) gsacc += __shfl_xor_sync(FULL, gsacc, s);
    float gstot = gsacc;
    const float4* bet = (const float4*)(beta + r * 128 + 64);
    float4 b0 = __ldg(bet + 2 * m);
    float4 b1 = __ldg(bet + 2 * m + 1);
    float dot = o[0] * b0.x + o[1] * b0.y + o[2] * b0.z + o[3] * b0.w
              + o[4] * b1.x + o[5] * b1.y + o[6] * b1.z + o[7] * b1.w;
    #pragma unroll
    for (int s = 4; s; s >>= 1) dot += __shfl_xor_sync(FULL, dot, s);
    float ga = gstot / fmaxf((float)deg, 1.f) + dot;
    float gate = 1.f / (1.f + __expf(-ga));
    if (lane < 8) {
        const float4* hpn = (const float4*)g_hp + ((size_t)r * NN + n) * 16;
        float4 h0 = __ldg(hpn + 2 * m);
        float4 h1 = __ldg(hpn + 2 * m + 1);
        float4* res = (float4*)(g_res + (size_t)n * 192 + r * 64);
        float gi = 1.f - gate;
        res[2 * m]     = make_float4(gate * o[0] + gi * h0.x, gate * o[1] + gi * h0.y,
                                     gate * o[2] + gi * h0.z, gate * o[3] + gi * h0.w);
        res[2 * m + 1] = make_float4(gate * o[4] + gi * h1.x, gate * o[5] + gi * h1.y,
                                     gate * o[6] + gi * h1.z, gate * o[7] + gi * h1.w);
    }
}

// ---------------- k_final: [N,192]x[192,64], register-tiled, f32x2 ----------
__global__ __launch_bounds__(256) void k_final(
    const float* __restrict__ lin_w, const float* __restrict__ lin_b,
    float* __restrict__ out)
{
    __shared__ float sXT[32 * 132];
    __shared__ float sW[32 * 64];
    int tid = threadIdx.x;
    int base = blockIdx.x * 128;
    int cx = (tid & 15) * 4;
    int ry = (tid >> 4) * 8;
    unsigned long long acc2[8][2];
    #pragma unroll
    for (int i = 0; i < 8; ++i) { acc2[i][0] = 0ull; acc2[i][1] = 0ull; }

    for (int kc = 0; kc < 6; ++kc) {
        __syncthreads();
        {
            int kk = tid & 31, nr = tid >> 5;
            for (int p = 0; p < 16; ++p) {
                int n = p * 8 + nr;
                int gn = base + n;
                sXT[kk * 132 + n] = (gn < NN) ? g_res[(size_t)gn * 192 + kc * 32 + kk] : 0.f;
            }
        }
        for (int i = tid; i < 2048; i += 256) sW[i] = lin_w[kc * 2048 + i];
        __syncthreads();
        #pragma unroll 8
        for (int k = 0; k < 32; ++k) {
            const float* xr = &sXT[k * 132 + ry];
            float4 a0 = *(const float4*)xr;
            float4 a1 = *(const float4*)(xr + 4);
            float4 b  = *(const float4*)&sW[k * 64 + cx];
            unsigned long long b01 = pack2(b.x, b.y);
            unsigned long long b23 = pack2(b.z, b.w);
            float av[8] = {a0.x, a0.y, a0.z, a0.w, a1.x, a1.y, a1.z, a1.w};
            #pragma unroll
            for (int i = 0; i < 8; ++i) {
                unsigned long long aa = packbc(av[i]);
                ffma2(acc2[i][0], aa, b01);
                ffma2(acc2[i][1], aa, b23);
            }
        }
    }
    float4 bia = *(const float4*)&lin_b[cx];
    #pragma unroll
    for (int i = 0; i < 8; ++i) {
        int n = base + ry + i;
        if (n < NN) {
            float2 v01 = unpack2(acc2[i][0]);
            float2 v23 = unpack2(acc2[i][1]);
            float4 o4;
            o4.x = v01.x + bia.x;
            o4.y = v01.y + bia.y;
            o4.z = v23.x + bia.z;
            o4.w = v23.y + bia.w;
            *(float4*)&out[(size_t)n * 64 + cx] = o4;
        }
    }
}

// ---------------- launch -----------------------------------------------------
extern "C" void kernel_launch(void* const* d_in, const int* in_sizes, int n_in,
                              void* d_out, int out_size)
{
    const float* h       = (const float*)d_in[0];
    const int*   src     = (const int*)  d_in[1];
    const int*   dst     = (const int*)  d_in[2];
    const float* d_w     = (const float*)d_in[3];
    const float* d_b     = (const float*)d_in[4];
    const float* w_w     = (const float*)d_in[5];
    const float* w_b     = (const float*)d_in[6];
    const float* atten_w = (const float*)d_in[7];
    const float* atten_b = (const float*)d_in[8];
    const float* beta    = (const float*)d_in[9];
    const float* lin_w   = (const float*)d_in[10];
    const float* lin_b   = (const float*)d_in[11];
    float* out = (float*)d_out;

    void* degp = nullptr;
    cudaGetSymbolAddress(&degp, g_deg);
    cudaMemsetAsync(degp, 0, M_TOT * sizeof(int));
    void* sstp = nullptr;
    cudaGetSymbolAddress(&sstp, g_sstat);
    cudaMemsetAsync(sstp, 0, 512 * sizeof(int));

    // 1: prep + hist
    k_fat1<<<NODE_BLKS + HIST_BLKS, 256>>>(h, d_w, d_b, w_w, w_b, dst);
    // 2: single-pass scan
    k_scan<<<NBLK, 256>>>();
    // 3: build + pq
    k_fat2<<<HIST_BLKS + PQ_BLKS, 256>>>(src, dst, atten_w, atten_b, beta);
    // 4: aggregate  (ncu capture slot)
    dim3 gaggr((NN + 7) / 8, RR);
    k_aggr<<<gaggr, 256>>>(beta);
    // 5: final GEMM
    k_final<<<NODE_BLKS, 256>>>(lin_w, lin_b, out);
}

// round 9
// speedup vs baseline: 1.0085x; 1.0085x over previous
#include <cuda_runtime.h>
#include <cuda_fp16.h>
#include <math.h>
#include <float.h>

// Problem constants (fixed by the dataset)
#define NN 100000
#define EE 1200000
#define RR 3
#define M_TOT (RR * NN)
#define NBLK ((M_TOT + 1023) / 1024)       // 293
#define EDGE4 (RR * EE / 4)                 // 900000
#define NODE_BLKS ((NN + 127) / 128)        // 782
#define HIST_BLKS ((EDGE4 + 255) / 256)     // 3516
#define PQ_BLKS ((NN + 7) / 8)              // 12500

// ---------------- scratch (device globals; no allocation allowed) ----------
__device__ float   g_tfeat[NN * 64];
__device__ float4  g_hp[RR * NN * 16];        // hp fp32
__device__ __half2 g_hp16[RR * NN * 32];      // hp fp16 (128B gather rows)
__device__ float4  g_p[RR * NN];
__device__ float4  g_q[RR * NN];
__device__ float   g_gs[RR * NN];
__device__ float   g_res[NN * 192];
// CSR
__device__ int     g_deg[M_TOT];
__device__ int     g_row[M_TOT];              // global start; after build -> end
__device__ int     g_srt[RR * EE];
// lookback scan state
__device__ int     g_sagg[512];
__device__ int     g_spre[512];
__device__ int     g_sstat[512];              // 0 none, 1 agg, 2 prefix

__device__ __forceinline__ float lrelu(float x) { return x >= 0.f ? x : 0.01f * x; }

__device__ __forceinline__ unsigned long long pack2(float lo, float hi) {
    unsigned long long v;
    asm("mov.b64 %0, {%1,%2};" : "=l"(v) : "f"(lo), "f"(hi));
    return v;
}
__device__ __forceinline__ unsigned long long packbc(float x) {
    unsigned long long v;
    asm("mov.b64 %0, {%1,%1};" : "=l"(v) : "f"(x));
    return v;
}
__device__ __forceinline__ void ffma2(unsigned long long& d,
                                      unsigned long long a, unsigned long long b) {
    asm("fma.rn.f32x2 %0, %1, %2, %0;" : "+l"(d) : "l"(a), "l"(b));
}
__device__ __forceinline__ float2 unpack2(unsigned long long v) {
    float lo, hi;
    asm("mov.b64 {%0,%1}, %2;" : "=f"(lo), "=f"(hi) : "l"(v));
    return make_float2(lo, hi);
}

// ---------------- fat1: prep (blocks 0..781) + hist (rest) -----------------
__global__ __launch_bounds__(256) void k_fat1(
    const float* __restrict__ h, const float* __restrict__ d_w,
    const float* __restrict__ d_b, const float* __restrict__ w_w,
    const float* __restrict__ w_b, const int* __restrict__ dst)
{
    __shared__ float sHT[64 * 132];   // [k][n] padded
    __shared__ float sW[32 * 64];
    int tid = threadIdx.x;

    if (blockIdx.x >= NODE_BLKS) {
        int i = (blockIdx.x - NODE_BLKS) * 256 + tid;
        if (i < EDGE4) {
            int4 d4 = ((const int4*)dst)[i];
            int rb = (4 * i) / EE * NN;
            atomicAdd(&g_deg[rb + d4.x], 1);
            atomicAdd(&g_deg[rb + d4.y], 1);
            atomicAdd(&g_deg[rb + d4.z], 1);
            atomicAdd(&g_deg[rb + d4.w], 1);
        }
        return;
    }

    int base = blockIdx.x * 128;
    {
        int kk = tid & 63, nr = tid >> 6;
        for (int p = 0; p < 32; ++p) {
            int n = p * 4 + nr;
            int gn = base + n;
            sHT[kk * 132 + n] = (gn < NN) ? h[(size_t)gn * 64 + kk] : 0.f;
        }
    }
    int cx = (tid & 15) * 4;
    int ry = (tid >> 4) * 8;

    for (int mat = 0; mat < 4; ++mat) {
        const float* Wsrc = (mat == 0) ? d_w : (w_w + (mat - 1) * 4096);
        unsigned long long acc2[8][2];
        #pragma unroll
        for (int i = 0; i < 8; ++i) { acc2[i][0] = 0ull; acc2[i][1] = 0ull; }

        for (int kc = 0; kc < 2; ++kc) {
            __syncthreads();
            for (int i = tid; i < 2048; i += 256) sW[i] = Wsrc[kc * 2048 + i];
            __syncthreads();
            #pragma unroll 8
            for (int k = 0; k < 32; ++k) {
                const float* hr = &sHT[(kc * 32 + k) * 132 + ry];
                float4 a0 = *(const float4*)hr;
                float4 a1 = *(const float4*)(hr + 4);
                float4 b  = *(const float4*)&sW[k * 64 + cx];
                unsigned long long b01 = pack2(b.x, b.y);
                unsigned long long b23 = pack2(b.z, b.w);
                float av[8] = {a0.x, a0.y, a0.z, a0.w, a1.x, a1.y, a1.z, a1.w};
                #pragma unroll
                for (int i = 0; i < 8; ++i) {
                    unsigned long long aa = packbc(av[i]);
                    ffma2(acc2[i][0], aa, b01);
                    ffma2(acc2[i][1], aa, b23);
                }
            }
        }
        if (mat == 0) {
            float4 bia = *(const float4*)&d_b[cx];
            #pragma unroll
            for (int i = 0; i < 8; ++i) {
                int n = base + ry + i;
                if (n < NN) {
                    float2 v01 = unpack2(acc2[i][0]);
                    float2 v23 = unpack2(acc2[i][1]);
                    float4 t4;
                    t4.x = tanhf(2.f * (v01.x + bia.x));
                    t4.y = tanhf(2.f * (v01.y + bia.y));
                    t4.z = tanhf(2.f * (v23.x + bia.z));
                    t4.w = tanhf(2.f * (v23.y + bia.w));
                    *(float4*)&g_tfeat[(size_t)n * 64 + cx] = t4;
                }
            }
        } else {
            int r = mat - 1;
            float4 bia = *(const float4*)&w_b[r * 64 + cx];
            #pragma unroll
            for (int i = 0; i < 8; ++i) {
                int n = base + ry + i;
                if (n < NN) {
                    float2 v01 = unpack2(acc2[i][0]);
                    float2 v23 = unpack2(acc2[i][1]);
                    float4 hp4;
                    hp4.x = v01.x + bia.x;
                    hp4.y = v01.y + bia.y;
                    hp4.z = v23.x + bia.z;
                    hp4.w = v23.y + bia.w;
                    g_hp[((size_t)r * NN + n) * 16 + (cx >> 2)] = hp4;
                    __half2* p16 = &g_hp16[((size_t)r * NN + n) * 32 + (cx >> 1)];
                    p16[0] = __floats2half2_rn(hp4.x, hp4.y);
                    p16[1] = __floats2half2_rn(hp4.z, hp4.w);
                }
            }
        }
    }
}

// ---------------- single-pass decoupled-lookback scan -----------------------
__global__ __launch_bounds__(256) void k_scan() {
    __shared__ int sS[256];
    __shared__ int sExcl;
    int b = blockIdx.x;
    int tid = threadIdx.x;
    int base = b * 1024 + tid * 4;
    int v[4]; int s = 0;
    #pragma unroll
    for (int j = 0; j < 4; ++j) {
        v[j] = (base + j < M_TOT) ? g_deg[base + j] : 0;
        s += v[j];
    }
    sS[tid] = s;
    __syncthreads();
    for (int off = 1; off < 256; off <<= 1) {
        int t = (tid >= off) ? sS[tid - off] : 0;
        __syncthreads();
        sS[tid] += t;
        __syncthreads();
    }
    int run = sS[tid] - s;
    int bsum = sS[255];
    if (tid == 0) {
        *(volatile int*)&g_sagg[b] = bsum;
        __threadfence();
        *(volatile int*)&g_sstat[b] = 1;
        int excl = 0;
        if (b > 0) {
            int j = b - 1;
            while (true) {
                int st;
                while ((st = *(volatile int*)&g_sstat[j]) == 0) __nanosleep(40);
                if (st == 2) { excl += *(volatile int*)&g_spre[j]; break; }
                excl += *(volatile int*)&g_sagg[j];
                if (--j < 0) break;
            }
        }
        *(volatile int*)&g_spre[b] = excl + bsum;
        __threadfence();
        *(volatile int*)&g_sstat[b] = 2;
        sExcl = excl;
    }
    __syncthreads();
    int run2 = run + sExcl;
    #pragma unroll
    for (int j = 0; j < 4; ++j) {
        if (base + j < M_TOT) g_row[base + j] = run2;
        run2 += v[j];
    }
}

// ---------------- fat2: build (blocks 0..3515) + pq (rest) ------------------
__global__ __launch_bounds__(256) void k_fat2(
    const int* __restrict__ src, const int* __restrict__ dst,
    const float* __restrict__ atten_w, const float* __restrict__ atten_b,
    const float* __restrict__ beta)
{
    const unsigned FULL = 0xffffffffu;
    int tid = threadIdx.x;
    if (blockIdx.x < HIST_BLKS) {
        int i = blockIdx.x * 256 + tid;
        if (i >= EDGE4) return;
        int4 d4 = ((const int4*)dst)[i];
        int4 s4 = ((const int4*)src)[i];
        int rb = (4 * i) / EE * NN;
        g_srt[atomicAdd(&g_row[rb + d4.x], 1)] = s4.x;
        g_srt[atomicAdd(&g_row[rb + d4.y], 1)] = s4.y;
        g_srt[atomicAdd(&g_row[rb + d4.z], 1)] = s4.z;
        g_srt[atomicAdd(&g_row[rb + d4.w], 1)] = s4.w;
        return;
    }
    int n = (blockIdx.x - HIST_BLKS) * 8 + (tid >> 5);
    int lane = tid & 31;
    if (n >= NN) return;
    float t0 = g_tfeat[(size_t)n * 64 + lane];
    float t1 = g_tfeat[(size_t)n * 64 + 32 + lane];
    int j = lane & 15;
    #pragma unroll
    for (int r = 0; r < RR; ++r) {
        const float* hp = (const float*)&g_hp[((size_t)r * NN + n) * 16];
        float h0 = hp[lane], h1 = hp[lane + 32];
        float wa0 = __ldg(atten_w + r * 48 + j);
        float wa1 = __ldg(atten_w + r * 48 + 16 + j);
        float wa2 = __ldg(atten_w + r * 48 + 32 + j);
        float pA = h0 * wa0 + t0 * wa2;
        float pB = h1 * wa0 + t1 * wa2;
        float qA = h0 * wa1;
        float qB = h1 * wa1;
        #pragma unroll
        for (int s = 8; s; s >>= 1) {
            pA += __shfl_xor_sync(FULL, pA, s, 16);
            pB += __shfl_xor_sync(FULL, pB, s, 16);
            qA += __shfl_xor_sync(FULL, qA, s, 16);
            qB += __shfl_xor_sync(FULL, qB, s, 16);
        }
        float gsv = t0 * __ldg(beta + r * 128 + lane)
                  + t1 * __ldg(beta + r * 128 + 32 + lane);
        #pragma unroll
        for (int s = 16; s; s >>= 1) gsv += __shfl_xor_sync(FULL, gsv, s);
        if (j == 0) {
            int hh = lane >> 4;
            float ab = __ldg(atten_b + r);
            float* pp = (float*)&g_p[(size_t)r * NN + n];
            pp[hh]     = pA + ab;
            pp[hh + 2] = pB + ab;
            float* qq = (float*)&g_q[(size_t)r * NN + n];
            qq[hh]     = qA;
            qq[hh + 2] = qB;
        }
        if (lane == 0) g_gs[(size_t)r * NN + n] = gsv;
    }
}

// ---------------- aggregate: warp per (node, relation), HFMA2 ---------------
// superchunk of 32 edges: s_all lane-per-edge; p-loads and hp16 gathers all
// depend only on s_all (high MLP). Weighted sum accumulated in half2 via
// HFMA2 (2 MACs/instr, no CVTs) and flushed to fp32 per superchunk.
__global__ __launch_bounds__(256) void k_aggr(const float* __restrict__ beta)
{
    const unsigned FULL = 0xffffffffu;
    int warp = threadIdx.x >> 5;
    int lane = threadIdx.x & 31;
    int n = blockIdx.x * 8 + warp;
    int r = blockIdx.y;
    if (n >= NN) return;
    int idx = r * NN + n;
    int deg = g_deg[idx];
    int end = g_row[idx];            // build turned start -> end
    int start = end - deg;

    int m   = lane & 7;              // dim group: dims 8m..8m+7
    int qtr = lane >> 3;             // edge sub-slot in gather groups
    float qc = __ldg((const float*)g_q + (size_t)idx * 4 + (lane & 3));

    float acc[8];
    #pragma unroll
    for (int i = 0; i < 8; ++i) acc[i] = 0.f;
    float denacc = 0.f;
    float gsacc = 0.f;

    const float* pbase  = (const float*)g_p + (size_t)r * NN * 4;
    const float* gsbase = g_gs + (size_t)r * NN;
    const uint4* hpbase16 = (const uint4*)g_hp16 + (size_t)r * NN * 8;

    for (int sc = 0; sc < deg; sc += 32) {
        int cnt = deg - sc; if (cnt > 32) cnt = 32;
        // all edge ids for this superchunk, one coalesced load
        int s_all = (lane < cnt) ? __ldg(g_srt + start + sc + lane) : 0;
        // gs gather (parallel scattered loads)
        gsacc += (lane < cnt) ? __ldg(gsbase + s_all) : 0.f;
        // p loads + exp for 4 chunks of 8 edges (lane = 4*edgeInChunk + head)
        float exc[4];
        #pragma unroll
        for (int c = 0; c < 4; ++c) {
            int eo = c * 8 + (lane >> 2);
            int sx = __shfl_sync(FULL, s_all, eo);
            float pl = __ldg(pbase + (size_t)sx * 4 + (lane & 3));
            exc[c] = (eo < cnt) ? __expf(lrelu(pl + qc)) : 0.f;
            denacc += exc[c];
        }
        // hp16 gather: 8 groups x 4 edges, 8 lanes (m) per edge row.
        // fp16 accumulate (HFMA2), flushed after the superchunk.
        __half2 acch[4];
        #pragma unroll
        for (int i = 0; i < 4; ++i) acch[i] = __half2half2(__float2half(0.f));
        int nit = (cnt + 3) >> 2;
        #pragma unroll
        for (int g = 0; g < 8; ++g) {
            if (g >= nit) break;                           // warp-uniform
            int e0 = g * 4 + qtr;                          // edge 0..31
            int   sj = __shfl_sync(FULL, s_all, e0);
            float e  = __shfl_sync(FULL, exc[g >> 1],
                                   16 * (g & 1) + 4 * qtr + (m >> 1));
            __half2 eh = __float2half2_rn(e);
            uint4 hv = __ldg(hpbase16 + (size_t)sj * 8 + m);
            acch[0] = __hfma2(*(const __half2*)&hv.x, eh, acch[0]);
            acch[1] = __hfma2(*(const __half2*)&hv.y, eh, acch[1]);
            acch[2] = __hfma2(*(const __half2*)&hv.z, eh, acch[2]);
            acch[3] = __hfma2(*(const __half2*)&hv.w, eh, acch[3]);
        }
        #pragma unroll
        for (int i = 0; i < 4; ++i) {
            float2 t = __half22float2(acch[i]);
            acc[2 * i]     += t.x;
            acc[2 * i + 1] += t.y;
        }
    }
    // denom per head (lanes sharing lane&3 across edge slots: bits 2..4)
    #pragma unroll
    for (int s = 4; s < 32; s <<= 1) denacc += __shfl_xor_sync(FULL, denacc, s);
    float d = __shfl_sync(FULL, denacc, m >> 1);
    // merge the 4 quarter edge-sets
    #pragma unroll
    for (int i = 0; i < 8; ++i) {
        acc[i] += __shfl_xor_sync(FULL, acc[i], 8);
        acc[i] += __shfl_xor_sync(FULL, acc[i], 16);
    }
    float inv = 1.f / fmaxf(d, 1e-20f);
    float o[8];
    #pragma unroll
    for (int i = 0; i < 8; ++i) o[i] = acc[i] * inv;
    // gs total
    #pragma unroll
    for (int s = 16; s; s >>= 1) gsacc += __shfl_xor_sync(FULL, gsacc, s);
    float gstot = gsacc;
    const float4* bet = (const float4*)(beta + r * 128 + 64);
    float4 b0 = __ldg(bet + 2 * m);
    float4 b1 = __ldg(bet + 2 * m + 1);
    float dot = o[0] * b0.x + o[1] * b0.y + o[2] * b0.z + o[3] * b0.w
              + o[4] * b1.x + o[5] * b1.y + o[6] * b1.z + o[7] * b1.w;
    #pragma unroll
    for (int s = 4; s; s >>= 1) dot += __shfl_xor_sync(FULL, dot, s);
    float ga = gstot / fmaxf((float)deg, 1.f) + dot;
    float gate = 1.f / (1.f + __expf(-ga));
    if (lane < 8) {
        const float4* hpn = (const float4*)g_hp + ((size_t)r * NN + n) * 16;
        float4 h0 = __ldg(hpn + 2 * m);
        float4 h1 = __ldg(hpn + 2 * m + 1);
        float4* res = (float4*)(g_res + (size_t)n * 192 + r * 64);
        float gi = 1.f - gate;
        res[2 * m]     = make_float4(gate * o[0] + gi * h0.x, gate * o[1] + gi * h0.y,
                                     gate * o[2] + gi * h0.z, gate * o[3] + gi * h0.w);
        res[2 * m + 1] = make_float4(gate * o[4] + gi * h1.x, gate * o[5] + gi * h1.y,
                                     gate * o[6] + gi * h1.z, gate * o[7] + gi * h1.w);
    }
}

// ---------------- k_final: [N,192]x[192,64], register-tiled, f32x2 ----------
__global__ __launch_bounds__(256) void k_final(
    const float* __restrict__ lin_w, const float* __restrict__ lin_b,
    float* __restrict__ out)
{
    __shared__ float sXT[32 * 132];
    __shared__ float sW[32 * 64];
    int tid = threadIdx.x;
    int base = blockIdx.x * 128;
    int cx = (tid & 15) * 4;
    int ry = (tid >> 4) * 8;
    unsigned long long acc2[8][2];
    #pragma unroll
    for (int i = 0; i < 8; ++i) { acc2[i][0] = 0ull; acc2[i][1] = 0ull; }

    for (int kc = 0; kc < 6; ++kc) {
        __syncthreads();
        {
            int kk = tid & 31, nr = tid >> 5;
            for (int p = 0; p < 16; ++p) {
                int n = p * 8 + nr;
                int gn = base + n;
                sXT[kk * 132 + n] = (gn < NN) ? g_res[(size_t)gn * 192 + kc * 32 + kk] : 0.f;
            }
        }
        for (int i = tid; i < 2048; i += 256) sW[i] = lin_w[kc * 2048 + i];
        __syncthreads();
        #pragma unroll 8
        for (int k = 0; k < 32; ++k) {
            const float* xr = &sXT[k * 132 + ry];
            float4 a0 = *(const float4*)xr;
            float4 a1 = *(const float4*)(xr + 4);
            float4 b  = *(const float4*)&sW[k * 64 + cx];
            unsigned long long b01 = pack2(b.x, b.y);
            unsigned long long b23 = pack2(b.z, b.w);
            float av[8] = {a0.x, a0.y, a0.z, a0.w, a1.x, a1.y, a1.z, a1.w};
            #pragma unroll
            for (int i = 0; i < 8; ++i) {
                unsigned long long aa = packbc(av[i]);
                ffma2(acc2[i][0], aa, b01);
                ffma2(acc2[i][1], aa, b23);
            }
        }
    }
    float4 bia = *(const float4*)&lin_b[cx];
    #pragma unroll
    for (int i = 0; i < 8; ++i) {
        int n = base + ry + i;
        if (n < NN) {
            float2 v01 = unpack2(acc2[i][0]);
            float2 v23 = unpack2(acc2[i][1]);
            float4 o4;
            o4.x = v01.x + bia.x;
            o4.y = v01.y + bia.y;
            o4.z = v23.x + bia.z;
            o4.w = v23.y + bia.w;
            *(float4*)&out[(size_t)n * 64 + cx] = o4;
        }
    }
}

// ---------------- launch -----------------------------------------------------
extern "C" void kernel_launch(void* const* d_in, const int* in_sizes, int n_in,
                              void* d_out, int out_size)
{
    const float* h       = (const float*)d_in[0];
    const int*   src     = (const int*)  d_in[1];
    const int*   dst     = (const int*)  d_in[2];
    const float* d_w     = (const float*)d_in[3];
    const float* d_b     = (const float*)d_in[4];
    const float* w_w     = (const float*)d_in[5];
    const float* w_b     = (const float*)d_in[6];
    const float* atten_w = (const float*)d_in[7];
    const float* atten_b = (const float*)d_in[8];
    const float* beta    = (const float*)d_in[9];
    const float* lin_w   = (const float*)d_in[10];
    const float* lin_b   = (const float*)d_in[11];
    float* out = (float*)d_out;

    void* degp = nullptr;
    cudaGetSymbolAddress(&degp, g_deg);
    cudaMemsetAsync(degp, 0, M_TOT * sizeof(int));
    void* sstp = nullptr;
    cudaGetSymbolAddress(&sstp, g_sstat);
    cudaMemsetAsync(sstp, 0, 512 * sizeof(int));

    // 1: prep + hist
    k_fat1<<<NODE_BLKS + HIST_BLKS, 256>>>(h, d_w, d_b, w_w, w_b, dst);
    // 2: single-pass scan
    k_scan<<<NBLK, 256>>>();
    // 3: build + pq
    k_fat2<<<HIST_BLKS + PQ_BLKS, 256>>>(src, dst, atten_w, atten_b, beta);
    // 4: aggregate  (ncu capture slot)
    dim3 gaggr((NN + 7) / 8, RR);
    k_aggr<<<gaggr, 256>>>(beta);
    // 5: final GEMM
    k_final<<<NODE_BLKS, 256>>>(lin_w, lin_b, out);
}